// round 12
// baseline (speedup 1.0000x reference)
#include <cuda_runtime.h>
#include <math.h>

#define BATCHN 2
#define SEQ    2048
#define EMB    1024
#define NH     16
#define HD     64
#define BSROWS (BATCHN*SEQ)      /* 4096 */
#define QKVN   (3*EMB)           /* 3072 */
#define OUT_ELEMS (BSROWS*EMB)   /* 4194304 */
#define ATTN_ELEMS (134217728)   /* 2*16*2048*2048 */

// ---------------- scratch (device globals: no runtime allocation) ------------
__device__ float g_qkv[(size_t)BSROWS * QKVN];       // [B*S, 3E]
__device__ float g_ctx[(size_t)BSROWS * EMB];        // [B*S, E] attn output ctx
__device__ float g_m[(size_t)BATCHN * NH * SEQ];     // row max
__device__ float g_z[(size_t)BATCHN * NH * SEQ];     // row sum-exp
// fallbacks if harness output layout differs from (out, attn) concat
__device__ float g_attn_scratch[(size_t)ATTN_ELEMS];
__device__ float g_out_scratch[(size_t)OUT_ELEMS];

// ---------------- generic 64x64 tiled SGEMM with bias ------------------------
// C[M,N] = A[M,K] @ B[K,N] + bias[N]; M,N multiples of 64, K multiple of 16.
__global__ __launch_bounds__(256) void sgemm_bias_kernel(
    const float* __restrict__ A, const float* __restrict__ B,
    const float* __restrict__ bias, float* __restrict__ C,
    int M, int N, int K)
{
    __shared__ float As[16][68];   // [k][m] (transposed)
    __shared__ float Bs[16][68];   // [k][n]
    const int tx = threadIdx.x & 15, ty = threadIdx.x >> 4;
    const int m0 = blockIdx.y * 64, n0 = blockIdx.x * 64;

    float acc[4][4] = {};
    for (int k0 = 0; k0 < K; k0 += 16) {
        for (int i = threadIdx.x; i < 1024; i += 256) {
            int r = i >> 4, c = i & 15;
            As[c][r] = A[(size_t)(m0 + r) * K + (k0 + c)];
        }
        for (int i = threadIdx.x; i < 1024; i += 256) {
            int r = i >> 6, c = i & 63;
            Bs[r][c] = B[(size_t)(k0 + r) * N + (n0 + c)];
        }
        __syncthreads();
        #pragma unroll
        for (int kk = 0; kk < 16; kk++) {
            float4 a4 = *(const float4*)&As[kk][ty * 4];
            float4 b4 = *(const float4*)&Bs[kk][tx * 4];
            float av[4] = {a4.x, a4.y, a4.z, a4.w};
            float bv[4] = {b4.x, b4.y, b4.z, b4.w};
            #pragma unroll
            for (int i = 0; i < 4; i++)
                #pragma unroll
                for (int j = 0; j < 4; j++)
                    acc[i][j] = fmaf(av[i], bv[j], acc[i][j]);
        }
        __syncthreads();
    }
    float4 bb = *(const float4*)&bias[n0 + tx * 4];
    #pragma unroll
    for (int i = 0; i < 4; i++) {
        int m = m0 + ty * 4 + i;
        float4 o;
        o.x = acc[i][0] + bb.x;
        o.y = acc[i][1] + bb.y;
        o.z = acc[i][2] + bb.z;
        o.w = acc[i][3] + bb.w;
        *(float4*)&C[(size_t)m * N + n0 + tx * 4] = o;
    }
}

// ---------------- pass A: raw scores + online row max/sumexp -----------------
// grid: (SEQ/64, B*NH). One block owns 64 query rows across all 2048 keys.
__global__ __launch_bounds__(256) void attn_scores_kernel(
    const float* __restrict__ qkv, float* __restrict__ attn)
{
    __shared__ float Qs[64][68];   // [d][q]
    __shared__ float Ks[64][68];   // [d][k]
    const int tx = threadIdx.x & 15, ty = threadIdx.x >> 4;
    const int bh = blockIdx.y;
    const int b = bh >> 4, h = bh & 15;
    const int q0 = blockIdx.x * 64;
    const float slope = exp2f(-0.5f * (float)(h + 1));

    const float* qbase = qkv + (size_t)b * SEQ * QKVN + h * (3 * HD);
    // Q tile (transposed into smem), loaded once
    for (int i = threadIdx.x; i < 4096; i += 256) {
        int q = i >> 6, d = i & 63;
        Qs[d][q] = qbase[(size_t)(q0 + q) * QKVN + d];
    }

    float mrun[4], zrun[4];
    #pragma unroll
    for (int i = 0; i < 4; i++) { mrun[i] = -3.4e38f; zrun[i] = 0.0f; }

    float* arow = attn + (size_t)bh * SEQ * SEQ;

    for (int kt = 0; kt < SEQ; kt += 64) {
        __syncthreads();
        for (int i = threadIdx.x; i < 4096; i += 256) {
            int k = i >> 6, d = i & 63;
            Ks[d][k] = qbase[(size_t)(kt + k) * QKVN + HD + d];
        }
        __syncthreads();

        float acc[4][4] = {};
        #pragma unroll 8
        for (int d = 0; d < 64; d++) {
            float4 a4 = *(const float4*)&Qs[d][ty * 4];
            float4 c4 = *(const float4*)&Ks[d][tx * 4];
            float av[4] = {a4.x, a4.y, a4.z, a4.w};
            float cv[4] = {c4.x, c4.y, c4.z, c4.w};
            #pragma unroll
            for (int i = 0; i < 4; i++)
                #pragma unroll
                for (int j = 0; j < 4; j++)
                    acc[i][j] = fmaf(av[i], cv[j], acc[i][j]);
        }

        #pragma unroll
        for (int i = 0; i < 4; i++) {
            int q = q0 + ty * 4 + i;
            float s[4];
            #pragma unroll
            for (int j = 0; j < 4; j++) {
                int k = kt + tx * 4 + j;
                s[j] = acc[i][j] * 0.125f + slope * (float)(k - q);
            }
            // row max over this 64-wide tile (16 lanes share a row)
            float lm = fmaxf(fmaxf(s[0], s[1]), fmaxf(s[2], s[3]));
            #pragma unroll
            for (int off = 8; off > 0; off >>= 1)
                lm = fmaxf(lm, __shfl_xor_sync(0xffffffffu, lm, off, 16));
            float mnew = fmaxf(mrun[i], lm);
            float se = __expf(s[0] - mnew) + __expf(s[1] - mnew) +
                       __expf(s[2] - mnew) + __expf(s[3] - mnew);
            #pragma unroll
            for (int off = 8; off > 0; off >>= 1)
                se += __shfl_xor_sync(0xffffffffu, se, off, 16);
            zrun[i] = zrun[i] * __expf(mrun[i] - mnew) + se;
            mrun[i] = mnew;

            float4 o = {s[0], s[1], s[2], s[3]};
            *(float4*)&arow[(size_t)q * SEQ + kt + tx * 4] = o;
        }
    }

    if (tx == 0) {
        #pragma unroll
        for (int i = 0; i < 4; i++) {
            int q = q0 + ty * 4 + i;
            g_m[(size_t)bh * SEQ + q] = mrun[i];
            g_z[(size_t)bh * SEQ + q] = zrun[i];
        }
    }
}

// ---------------- pass B: normalize attn in-place + O = P @ V ----------------
__global__ __launch_bounds__(256) void attn_av_kernel(
    const float* __restrict__ qkv, float* __restrict__ attn)
{
    __shared__ float Ps[64][68];   // [k][q]
    __shared__ float Vs[64][68];   // [k][d]
    __shared__ float ms[64];
    __shared__ float rz[64];
    const int tx = threadIdx.x & 15, ty = threadIdx.x >> 4;
    const int bh = blockIdx.y;
    const int b = bh >> 4, h = bh & 15;
    const int q0 = blockIdx.x * 64;

    if (threadIdx.x < 64) {
        ms[threadIdx.x] = g_m[(size_t)bh * SEQ + q0 + threadIdx.x];
        rz[threadIdx.x] = 1.0f / g_z[(size_t)bh * SEQ + q0 + threadIdx.x];
    }

    const float* vbase = qkv + (size_t)b * SEQ * QKVN + h * (3 * HD) + 2 * HD;
    float* arow = attn + (size_t)bh * SEQ * SEQ + (size_t)q0 * SEQ;

    float acc[4][4] = {};
    for (int kt = 0; kt < SEQ; kt += 64) {
        __syncthreads();
        // read raw scores, normalize, write p back, stash transposed
        for (int i = threadIdx.x; i < 1024; i += 256) {
            int r = i >> 4, c4 = (i & 15) << 2;
            float4 s = *(const float4*)&arow[(size_t)r * SEQ + kt + c4];
            float m = ms[r], z = rz[r];
            float4 p;
            p.x = __expf(s.x - m) * z;
            p.y = __expf(s.y - m) * z;
            p.z = __expf(s.z - m) * z;
            p.w = __expf(s.w - m) * z;
            *(float4*)&arow[(size_t)r * SEQ + kt + c4] = p;
            Ps[c4 + 0][r] = p.x;
            Ps[c4 + 1][r] = p.y;
            Ps[c4 + 2][r] = p.z;
            Ps[c4 + 3][r] = p.w;
        }
        for (int i = threadIdx.x; i < 4096; i += 256) {
            int k = i >> 6, d = i & 63;
            Vs[k][d] = vbase[(size_t)(kt + k) * QKVN + d];
        }
        __syncthreads();

        #pragma unroll 8
        for (int kk = 0; kk < 64; kk++) {
            float4 p4 = *(const float4*)&Ps[kk][ty * 4];
            float4 v4 = *(const float4*)&Vs[kk][tx * 4];
            float pv[4] = {p4.x, p4.y, p4.z, p4.w};
            float vv[4] = {v4.x, v4.y, v4.z, v4.w};
            #pragma unroll
            for (int i = 0; i < 4; i++)
                #pragma unroll
                for (int j = 0; j < 4; j++)
                    acc[i][j] = fmaf(pv[i], vv[j], acc[i][j]);
        }
    }

    // ctx layout [B, S, H*D] so the out-projection is a plain GEMM
    #pragma unroll
    for (int i = 0; i < 4; i++) {
        int q = q0 + ty * 4 + i;
        float4 o = {acc[i][0], acc[i][1], acc[i][2], acc[i][3]};
        *(float4*)&g_ctx[(size_t)(b * SEQ + q) * EMB + h * HD + tx * 4] = o;
    }
}

// ---------------------------------- host -------------------------------------
extern "C" void kernel_launch(void* const* d_in, const int* in_sizes, int n_in,
                              void* d_out, int out_size)
{
    const float* x    = (const float*)d_in[0];   // [B,S,E]
    const float* Wqkv = (const float*)d_in[1];   // [E,3E]
    const float* bqkv = (const float*)d_in[2];   // [3E]
    const float* Wout = (const float*)d_in[3];   // [E,E]
    const float* bout = (const float*)d_in[4];   // [E]
    float* dout = (float*)d_out;

    float* qkv;  cudaGetSymbolAddress((void**)&qkv, g_qkv);
    float* ctx;  cudaGetSymbolAddress((void**)&ctx, g_ctx);

    float* out_ptr;
    float* attn_ptr;
    if (out_size >= OUT_ELEMS + ATTN_ELEMS) {
        // concatenated (out, attn) — expected layout
        out_ptr = dout;
        attn_ptr = dout + OUT_ELEMS;
    } else if (out_size == OUT_ELEMS) {
        out_ptr = dout;
        cudaGetSymbolAddress((void**)&attn_ptr, g_attn_scratch);
    } else {
        // attn-only output
        attn_ptr = dout;
        cudaGetSymbolAddress((void**)&out_ptr, g_out_scratch);
    }

    dim3 blk(256);
    // 1) QKV projection
    sgemm_bias_kernel<<<dim3(QKVN / 64, BSROWS / 64), blk>>>(
        x, Wqkv, bqkv, qkv, BSROWS, QKVN, EMB);
    // 2) raw scores + softmax stats
    attn_scores_kernel<<<dim3(SEQ / 64, BATCHN * NH), blk>>>(qkv, attn_ptr);
    // 3) normalize attn in-place + O = P @ V
    attn_av_kernel<<<dim3(SEQ / 64, BATCHN * NH), blk>>>(qkv, attn_ptr);
    // 4) output projection
    sgemm_bias_kernel<<<dim3(EMB / 64, BSROWS / 64), blk>>>(
        ctx, Wout, bout, out_ptr, BSROWS, EMB, EMB);
}

// round 13
// speedup vs baseline: 1.0424x; 1.0424x over previous
#include <cuda_runtime.h>
#include <math.h>

#define BATCHN 2
#define SEQ    2048
#define EMB    1024
#define NH     16
#define HD     64
#define BSROWS (BATCHN*SEQ)      /* 4096 */
#define QKVN   (3*EMB)           /* 3072 */
#define OUT_ELEMS (BSROWS*EMB)   /* 4194304 */
#define ATTN_ELEMS (134217728)   /* 2*16*2048*2048 */

// ---------------- scratch (device globals: no runtime allocation) ------------
__device__ float g_qkv[(size_t)BSROWS * QKVN];       // [B*S, 3E]
__device__ float g_ctx[(size_t)BSROWS * EMB];        // [B*S, E] attn output ctx
__device__ float g_m[(size_t)BATCHN * NH * SEQ];     // row max
__device__ float g_z[(size_t)BATCHN * NH * SEQ];     // row sum-exp
// fallbacks if harness output layout differs from (out, attn) concat
__device__ float g_attn_scratch[(size_t)ATTN_ELEMS];
__device__ float g_out_scratch[(size_t)OUT_ELEMS];

// ---------------- generic 64x64 tiled SGEMM with bias ------------------------
// C[M,N] = A[M,K] @ B[K,N] + bias[N]; M,N multiples of 64, K multiple of 16.
__global__ __launch_bounds__(256) void sgemm_bias_kernel(
    const float* __restrict__ A, const float* __restrict__ B,
    const float* __restrict__ bias, float* __restrict__ C,
    int M, int N, int K)
{
    __shared__ float As[16][68];   // [k][m] (transposed)
    __shared__ float Bs[16][68];   // [k][n]
    const int tx = threadIdx.x & 15, ty = threadIdx.x >> 4;
    const int m0 = blockIdx.y * 64, n0 = blockIdx.x * 64;

    float acc[4][4] = {};
    for (int k0 = 0; k0 < K; k0 += 16) {
        for (int i = threadIdx.x; i < 1024; i += 256) {
            int r = i >> 4, c = i & 15;
            As[c][r] = A[(size_t)(m0 + r) * K + (k0 + c)];
        }
        for (int i = threadIdx.x; i < 1024; i += 256) {
            int r = i >> 6, c = i & 63;
            Bs[r][c] = B[(size_t)(k0 + r) * N + (n0 + c)];
        }
        __syncthreads();
        #pragma unroll
        for (int kk = 0; kk < 16; kk++) {
            float4 a4 = *(const float4*)&As[kk][ty * 4];
            float4 b4 = *(const float4*)&Bs[kk][tx * 4];
            float av[4] = {a4.x, a4.y, a4.z, a4.w};
            float bv[4] = {b4.x, b4.y, b4.z, b4.w};
            #pragma unroll
            for (int i = 0; i < 4; i++)
                #pragma unroll
                for (int j = 0; j < 4; j++)
                    acc[i][j] = fmaf(av[i], bv[j], acc[i][j]);
        }
        __syncthreads();
    }
    float4 bb = *(const float4*)&bias[n0 + tx * 4];
    #pragma unroll
    for (int i = 0; i < 4; i++) {
        int m = m0 + ty * 4 + i;
        float4 o;
        o.x = acc[i][0] + bb.x;
        o.y = acc[i][1] + bb.y;
        o.z = acc[i][2] + bb.z;
        o.w = acc[i][3] + bb.w;
        *(float4*)&C[(size_t)m * N + n0 + tx * 4] = o;
    }
}

// ---------------- pass A: raw scores + online row max/sumexp -----------------
// grid: (SEQ/64, B*NH). One block owns 64 query rows across all 2048 keys.
__global__ __launch_bounds__(256) void attn_scores_kernel(
    const float* __restrict__ qkv, float* __restrict__ attn)
{
    __shared__ float Qs[64][68];   // [d][q]
    __shared__ float Ks[64][68];   // [d][k]
    const int tx = threadIdx.x & 15, ty = threadIdx.x >> 4;
    const int bh = blockIdx.y;
    const int b = bh >> 4, h = bh & 15;
    const int q0 = blockIdx.x * 64;
    const float slope = exp2f(-0.5f * (float)(h + 1));

    const float* qbase = qkv + (size_t)b * SEQ * QKVN + h * (3 * HD);
    // Q tile (transposed into smem), loaded once
    for (int i = threadIdx.x; i < 4096; i += 256) {
        int q = i >> 6, d = i & 63;
        Qs[d][q] = qbase[(size_t)(q0 + q) * QKVN + d];
    }

    float mrun[4], zrun[4];
    #pragma unroll
    for (int i = 0; i < 4; i++) { mrun[i] = -3.4e38f; zrun[i] = 0.0f; }

    float* arow = attn + (size_t)bh * SEQ * SEQ;

    for (int kt = 0; kt < SEQ; kt += 64) {
        __syncthreads();
        for (int i = threadIdx.x; i < 4096; i += 256) {
            int k = i >> 6, d = i & 63;
            Ks[d][k] = qbase[(size_t)(kt + k) * QKVN + HD + d];
        }
        __syncthreads();

        float acc[4][4] = {};
        #pragma unroll 8
        for (int d = 0; d < 64; d++) {
            float4 a4 = *(const float4*)&Qs[d][ty * 4];
            float4 c4 = *(const float4*)&Ks[d][tx * 4];
            float av[4] = {a4.x, a4.y, a4.z, a4.w};
            float cv[4] = {c4.x, c4.y, c4.z, c4.w};
            #pragma unroll
            for (int i = 0; i < 4; i++)
                #pragma unroll
                for (int j = 0; j < 4; j++)
                    acc[i][j] = fmaf(av[i], cv[j], acc[i][j]);
        }

        #pragma unroll
        for (int i = 0; i < 4; i++) {
            int q = q0 + ty * 4 + i;
            float s[4];
            #pragma unroll
            for (int j = 0; j < 4; j++) {
                int k = kt + tx * 4 + j;
                s[j] = acc[i][j] * 0.125f + slope * (float)(k - q);
            }
            // row max over this 64-wide tile (16 lanes share a row)
            float lm = fmaxf(fmaxf(s[0], s[1]), fmaxf(s[2], s[3]));
            #pragma unroll
            for (int off = 8; off > 0; off >>= 1)
                lm = fmaxf(lm, __shfl_xor_sync(0xffffffffu, lm, off, 16));
            float mnew = fmaxf(mrun[i], lm);
            float se = __expf(s[0] - mnew) + __expf(s[1] - mnew) +
                       __expf(s[2] - mnew) + __expf(s[3] - mnew);
            #pragma unroll
            for (int off = 8; off > 0; off >>= 1)
                se += __shfl_xor_sync(0xffffffffu, se, off, 16);
            zrun[i] = zrun[i] * __expf(mrun[i] - mnew) + se;
            mrun[i] = mnew;

            float4 o = {s[0], s[1], s[2], s[3]};
            *(float4*)&arow[(size_t)q * SEQ + kt + tx * 4] = o;
        }
    }

    if (tx == 0) {
        #pragma unroll
        for (int i = 0; i < 4; i++) {
            int q = q0 + ty * 4 + i;
            g_m[(size_t)bh * SEQ + q] = mrun[i];
            g_z[(size_t)bh * SEQ + q] = zrun[i];
        }
    }
}

// ---------------- pass B: normalize attn in-place + O = P @ V ----------------
__global__ __launch_bounds__(256) void attn_av_kernel(
    const float* __restrict__ qkv, float* __restrict__ attn)
{
    __shared__ float Ps[64][68];   // [k][q]
    __shared__ float Vs[64][68];   // [k][d]
    __shared__ float ms[64];
    __shared__ float rz[64];
    const int tx = threadIdx.x & 15, ty = threadIdx.x >> 4;
    const int bh = blockIdx.y;
    const int b = bh >> 4, h = bh & 15;
    const int q0 = blockIdx.x * 64;

    if (threadIdx.x < 64) {
        ms[threadIdx.x] = g_m[(size_t)bh * SEQ + q0 + threadIdx.x];
        rz[threadIdx.x] = 1.0f / g_z[(size_t)bh * SEQ + q0 + threadIdx.x];
    }

    const float* vbase = qkv + (size_t)b * SEQ * QKVN + h * (3 * HD) + 2 * HD;
    float* arow = attn + (size_t)bh * SEQ * SEQ + (size_t)q0 * SEQ;

    float acc[4][4] = {};
    for (int kt = 0; kt < SEQ; kt += 64) {
        __syncthreads();
        // read raw scores, normalize, write p back, stash transposed
        for (int i = threadIdx.x; i < 1024; i += 256) {
            int r = i >> 4, c4 = (i & 15) << 2;
            float4 s = *(const float4*)&arow[(size_t)r * SEQ + kt + c4];
            float m = ms[r], z = rz[r];
            float4 p;
            p.x = __expf(s.x - m) * z;
            p.y = __expf(s.y - m) * z;
            p.z = __expf(s.z - m) * z;
            p.w = __expf(s.w - m) * z;
            *(float4*)&arow[(size_t)r * SEQ + kt + c4] = p;
            Ps[c4 + 0][r] = p.x;
            Ps[c4 + 1][r] = p.y;
            Ps[c4 + 2][r] = p.z;
            Ps[c4 + 3][r] = p.w;
        }
        for (int i = threadIdx.x; i < 4096; i += 256) {
            int k = i >> 6, d = i & 63;
            Vs[k][d] = vbase[(size_t)(kt + k) * QKVN + d];
        }
        __syncthreads();

        #pragma unroll 8
        for (int kk = 0; kk < 64; kk++) {
            float4 p4 = *(const float4*)&Ps[kk][ty * 4];
            float4 v4 = *(const float4*)&Vs[kk][tx * 4];
            float pv[4] = {p4.x, p4.y, p4.z, p4.w};
            float vv[4] = {v4.x, v4.y, v4.z, v4.w};
            #pragma unroll
            for (int i = 0; i < 4; i++)
                #pragma unroll
                for (int j = 0; j < 4; j++)
                    acc[i][j] = fmaf(pv[i], vv[j], acc[i][j]);
        }
    }

    // ctx layout [B, S, H*D] so the out-projection is a plain GEMM
    #pragma unroll
    for (int i = 0; i < 4; i++) {
        int q = q0 + ty * 4 + i;
        float4 o = {acc[i][0], acc[i][1], acc[i][2], acc[i][3]};
        *(float4*)&g_ctx[(size_t)(b * SEQ + q) * EMB + h * HD + tx * 4] = o;
    }
}

// ---------------------------------- host -------------------------------------
extern "C" void kernel_launch(void* const* d_in, const int* in_sizes, int n_in,
                              void* d_out, int out_size)
{
    const float* x    = (const float*)d_in[0];   // [B,S,E]
    const float* Wqkv = (const float*)d_in[1];   // [E,3E]
    const float* bqkv = (const float*)d_in[2];   // [3E]
    const float* Wout = (const float*)d_in[3];   // [E,E]
    const float* bout = (const float*)d_in[4];   // [E]
    float* dout = (float*)d_out;

    float* qkv;  cudaGetSymbolAddress((void**)&qkv, g_qkv);
    float* ctx;  cudaGetSymbolAddress((void**)&ctx, g_ctx);

    float* out_ptr;
    float* attn_ptr;
    if (out_size >= OUT_ELEMS + ATTN_ELEMS) {
        // concatenated (out, attn) — expected layout
        out_ptr = dout;
        attn_ptr = dout + OUT_ELEMS;
    } else if (out_size == OUT_ELEMS) {
        out_ptr = dout;
        cudaGetSymbolAddress((void**)&attn_ptr, g_attn_scratch);
    } else {
        // attn-only output
        attn_ptr = dout;
        cudaGetSymbolAddress((void**)&out_ptr, g_out_scratch);
    }

    dim3 blk(256);
    // 1) QKV projection
    sgemm_bias_kernel<<<dim3(QKVN / 64, BSROWS / 64), blk>>>(
        x, Wqkv, bqkv, qkv, BSROWS, QKVN, EMB);
    // 2) raw scores + softmax stats
    attn_scores_kernel<<<dim3(SEQ / 64, BATCHN * NH), blk>>>(qkv, attn_ptr);
    // 3) normalize attn in-place + O = P @ V
    attn_av_kernel<<<dim3(SEQ / 64, BATCHN * NH), blk>>>(qkv, attn_ptr);
    // 4) output projection
    sgemm_bias_kernel<<<dim3(EMB / 64, BSROWS / 64), blk>>>(
        ctx, Wout, bout, out_ptr, BSROWS, EMB, EMB);
}

// round 14
// speedup vs baseline: 1.0432x; 1.0008x over previous
#include <cuda_runtime.h>
#include <math.h>

#define BATCHN 2
#define SEQ    2048
#define EMB    1024
#define NH     16
#define HD     64
#define BSROWS (BATCHN*SEQ)      /* 4096 */
#define QKVN   (3*EMB)           /* 3072 */
#define OUT_ELEMS (BSROWS*EMB)   /* 4194304 */
#define ATTN_ELEMS (134217728)   /* 2*16*2048*2048 */

// ---------------- scratch (device globals: no runtime allocation) ------------
__device__ float g_qkv[(size_t)BSROWS * QKVN];       // [B*S, 3E]
__device__ float g_ctx[(size_t)BSROWS * EMB];        // [B*S, E] attn output ctx
__device__ float g_m[(size_t)BATCHN * NH * SEQ];     // row max
__device__ float g_z[(size_t)BATCHN * NH * SEQ];     // row sum-exp
// fallbacks if harness output layout differs from (out, attn) concat
__device__ float g_attn_scratch[(size_t)ATTN_ELEMS];
__device__ float g_out_scratch[(size_t)OUT_ELEMS];

// ---------------- generic 64x64 tiled SGEMM with bias ------------------------
// C[M,N] = A[M,K] @ B[K,N] + bias[N]; M,N multiples of 64, K multiple of 16.
__global__ __launch_bounds__(256) void sgemm_bias_kernel(
    const float* __restrict__ A, const float* __restrict__ B,
    const float* __restrict__ bias, float* __restrict__ C,
    int M, int N, int K)
{
    __shared__ float As[16][68];   // [k][m] (transposed)
    __shared__ float Bs[16][68];   // [k][n]
    const int tx = threadIdx.x & 15, ty = threadIdx.x >> 4;
    const int m0 = blockIdx.y * 64, n0 = blockIdx.x * 64;

    float acc[4][4] = {};
    for (int k0 = 0; k0 < K; k0 += 16) {
        for (int i = threadIdx.x; i < 1024; i += 256) {
            int r = i >> 4, c = i & 15;
            As[c][r] = A[(size_t)(m0 + r) * K + (k0 + c)];
        }
        for (int i = threadIdx.x; i < 1024; i += 256) {
            int r = i >> 6, c = i & 63;
            Bs[r][c] = B[(size_t)(k0 + r) * N + (n0 + c)];
        }
        __syncthreads();
        #pragma unroll
        for (int kk = 0; kk < 16; kk++) {
            float4 a4 = *(const float4*)&As[kk][ty * 4];
            float4 b4 = *(const float4*)&Bs[kk][tx * 4];
            float av[4] = {a4.x, a4.y, a4.z, a4.w};
            float bv[4] = {b4.x, b4.y, b4.z, b4.w};
            #pragma unroll
            for (int i = 0; i < 4; i++)
                #pragma unroll
                for (int j = 0; j < 4; j++)
                    acc[i][j] = fmaf(av[i], bv[j], acc[i][j]);
        }
        __syncthreads();
    }
    float4 bb = *(const float4*)&bias[n0 + tx * 4];
    #pragma unroll
    for (int i = 0; i < 4; i++) {
        int m = m0 + ty * 4 + i;
        float4 o;
        o.x = acc[i][0] + bb.x;
        o.y = acc[i][1] + bb.y;
        o.z = acc[i][2] + bb.z;
        o.w = acc[i][3] + bb.w;
        *(float4*)&C[(size_t)m * N + n0 + tx * 4] = o;
    }
}

// ---------------- pass A: raw scores + online row max/sumexp -----------------
// grid: (SEQ/64, B*NH). One block owns 64 query rows across all 2048 keys.
__global__ __launch_bounds__(256) void attn_scores_kernel(
    const float* __restrict__ qkv, float* __restrict__ attn)
{
    __shared__ float Qs[64][68];   // [d][q]
    __shared__ float Ks[64][68];   // [d][k]
    const int tx = threadIdx.x & 15, ty = threadIdx.x >> 4;
    const int bh = blockIdx.y;
    const int b = bh >> 4, h = bh & 15;
    const int q0 = blockIdx.x * 64;
    const float slope = exp2f(-0.5f * (float)(h + 1));

    const float* qbase = qkv + (size_t)b * SEQ * QKVN + h * (3 * HD);
    // Q tile (transposed into smem), loaded once
    for (int i = threadIdx.x; i < 4096; i += 256) {
        int q = i >> 6, d = i & 63;
        Qs[d][q] = qbase[(size_t)(q0 + q) * QKVN + d];
    }

    float mrun[4], zrun[4];
    #pragma unroll
    for (int i = 0; i < 4; i++) { mrun[i] = -3.4e38f; zrun[i] = 0.0f; }

    float* arow = attn + (size_t)bh * SEQ * SEQ;

    for (int kt = 0; kt < SEQ; kt += 64) {
        __syncthreads();
        for (int i = threadIdx.x; i < 4096; i += 256) {
            int k = i >> 6, d = i & 63;
            Ks[d][k] = qbase[(size_t)(kt + k) * QKVN + HD + d];
        }
        __syncthreads();

        float acc[4][4] = {};
        #pragma unroll 8
        for (int d = 0; d < 64; d++) {
            float4 a4 = *(const float4*)&Qs[d][ty * 4];
            float4 c4 = *(const float4*)&Ks[d][tx * 4];
            float av[4] = {a4.x, a4.y, a4.z, a4.w};
            float cv[4] = {c4.x, c4.y, c4.z, c4.w};
            #pragma unroll
            for (int i = 0; i < 4; i++)
                #pragma unroll
                for (int j = 0; j < 4; j++)
                    acc[i][j] = fmaf(av[i], cv[j], acc[i][j]);
        }

        #pragma unroll
        for (int i = 0; i < 4; i++) {
            int q = q0 + ty * 4 + i;
            float s[4];
            #pragma unroll
            for (int j = 0; j < 4; j++) {
                int k = kt + tx * 4 + j;
                s[j] = acc[i][j] * 0.125f + slope * (float)(k - q);
            }
            // row max over this 64-wide tile (16 lanes share a row)
            float lm = fmaxf(fmaxf(s[0], s[1]), fmaxf(s[2], s[3]));
            #pragma unroll
            for (int off = 8; off > 0; off >>= 1)
                lm = fmaxf(lm, __shfl_xor_sync(0xffffffffu, lm, off, 16));
            float mnew = fmaxf(mrun[i], lm);
            float se = __expf(s[0] - mnew) + __expf(s[1] - mnew) +
                       __expf(s[2] - mnew) + __expf(s[3] - mnew);
            #pragma unroll
            for (int off = 8; off > 0; off >>= 1)
                se += __shfl_xor_sync(0xffffffffu, se, off, 16);
            zrun[i] = zrun[i] * __expf(mrun[i] - mnew) + se;
            mrun[i] = mnew;

            float4 o = {s[0], s[1], s[2], s[3]};
            *(float4*)&arow[(size_t)q * SEQ + kt + tx * 4] = o;
        }
    }

    if (tx == 0) {
        #pragma unroll
        for (int i = 0; i < 4; i++) {
            int q = q0 + ty * 4 + i;
            g_m[(size_t)bh * SEQ + q] = mrun[i];
            g_z[(size_t)bh * SEQ + q] = zrun[i];
        }
    }
}

// ---------------- pass B: normalize attn in-place + O = P @ V ----------------
__global__ __launch_bounds__(256) void attn_av_kernel(
    const float* __restrict__ qkv, float* __restrict__ attn)
{
    __shared__ float Ps[64][68];   // [k][q]
    __shared__ float Vs[64][68];   // [k][d]
    __shared__ float ms[64];
    __shared__ float rz[64];
    const int tx = threadIdx.x & 15, ty = threadIdx.x >> 4;
    const int bh = blockIdx.y;
    const int b = bh >> 4, h = bh & 15;
    const int q0 = blockIdx.x * 64;

    if (threadIdx.x < 64) {
        ms[threadIdx.x] = g_m[(size_t)bh * SEQ + q0 + threadIdx.x];
        rz[threadIdx.x] = 1.0f / g_z[(size_t)bh * SEQ + q0 + threadIdx.x];
    }

    const float* vbase = qkv + (size_t)b * SEQ * QKVN + h * (3 * HD) + 2 * HD;
    float* arow = attn + (size_t)bh * SEQ * SEQ + (size_t)q0 * SEQ;

    float acc[4][4] = {};
    for (int kt = 0; kt < SEQ; kt += 64) {
        __syncthreads();
        // read raw scores, normalize, write p back, stash transposed
        for (int i = threadIdx.x; i < 1024; i += 256) {
            int r = i >> 4, c4 = (i & 15) << 2;
            float4 s = *(const float4*)&arow[(size_t)r * SEQ + kt + c4];
            float m = ms[r], z = rz[r];
            float4 p;
            p.x = __expf(s.x - m) * z;
            p.y = __expf(s.y - m) * z;
            p.z = __expf(s.z - m) * z;
            p.w = __expf(s.w - m) * z;
            *(float4*)&arow[(size_t)r * SEQ + kt + c4] = p;
            Ps[c4 + 0][r] = p.x;
            Ps[c4 + 1][r] = p.y;
            Ps[c4 + 2][r] = p.z;
            Ps[c4 + 3][r] = p.w;
        }
        for (int i = threadIdx.x; i < 4096; i += 256) {
            int k = i >> 6, d = i & 63;
            Vs[k][d] = vbase[(size_t)(kt + k) * QKVN + d];
        }
        __syncthreads();

        #pragma unroll 8
        for (int kk = 0; kk < 64; kk++) {
            float4 p4 = *(const float4*)&Ps[kk][ty * 4];
            float4 v4 = *(const float4*)&Vs[kk][tx * 4];
            float pv[4] = {p4.x, p4.y, p4.z, p4.w};
            float vv[4] = {v4.x, v4.y, v4.z, v4.w};
            #pragma unroll
            for (int i = 0; i < 4; i++)
                #pragma unroll
                for (int j = 0; j < 4; j++)
                    acc[i][j] = fmaf(pv[i], vv[j], acc[i][j]);
        }
    }

    // ctx layout [B, S, H*D] so the out-projection is a plain GEMM
    #pragma unroll
    for (int i = 0; i < 4; i++) {
        int q = q0 + ty * 4 + i;
        float4 o = {acc[i][0], acc[i][1], acc[i][2], acc[i][3]};
        *(float4*)&g_ctx[(size_t)(b * SEQ + q) * EMB + h * HD + tx * 4] = o;
    }
}

// ---------------------------------- host -------------------------------------
extern "C" void kernel_launch(void* const* d_in, const int* in_sizes, int n_in,
                              void* d_out, int out_size)
{
    const float* x    = (const float*)d_in[0];   // [B,S,E]
    const float* Wqkv = (const float*)d_in[1];   // [E,3E]
    const float* bqkv = (const float*)d_in[2];   // [3E]
    const float* Wout = (const float*)d_in[3];   // [E,E]
    const float* bout = (const float*)d_in[4];   // [E]
    float* dout = (float*)d_out;

    float* qkv;  cudaGetSymbolAddress((void**)&qkv, g_qkv);
    float* ctx;  cudaGetSymbolAddress((void**)&ctx, g_ctx);

    float* out_ptr;
    float* attn_ptr;
    if (out_size >= OUT_ELEMS + ATTN_ELEMS) {
        // concatenated (out, attn) — expected layout
        out_ptr = dout;
        attn_ptr = dout + OUT_ELEMS;
    } else if (out_size == OUT_ELEMS) {
        out_ptr = dout;
        cudaGetSymbolAddress((void**)&attn_ptr, g_attn_scratch);
    } else {
        // attn-only output
        attn_ptr = dout;
        cudaGetSymbolAddress((void**)&out_ptr, g_out_scratch);
    }

    dim3 blk(256);
    // 1) QKV projection
    sgemm_bias_kernel<<<dim3(QKVN / 64, BSROWS / 64), blk>>>(
        x, Wqkv, bqkv, qkv, BSROWS, QKVN, EMB);
    // 2) raw scores + softmax stats
    attn_scores_kernel<<<dim3(SEQ / 64, BATCHN * NH), blk>>>(qkv, attn_ptr);
    // 3) normalize attn in-place + O = P @ V
    attn_av_kernel<<<dim3(SEQ / 64, BATCHN * NH), blk>>>(qkv, attn_ptr);
    // 4) output projection
    sgemm_bias_kernel<<<dim3(EMB / 64, BSROWS / 64), blk>>>(
        ctx, Wout, bout, out_ptr, BSROWS, EMB, EMB);
}

// round 15
// speedup vs baseline: 1.0437x; 1.0005x over previous
#include <cuda_runtime.h>
#include <math.h>

#define BATCHN 2
#define SEQ    2048
#define EMB    1024
#define NH     16
#define HD     64
#define BSROWS (BATCHN*SEQ)      /* 4096 */
#define QKVN   (3*EMB)           /* 3072 */
#define OUT_ELEMS (BSROWS*EMB)   /* 4194304 */
#define ATTN_ELEMS (134217728)   /* 2*16*2048*2048 */

// ---------------- scratch (device globals: no runtime allocation) ------------
__device__ float g_qkv[(size_t)BSROWS * QKVN];       // [B*S, 3E]
__device__ float g_ctx[(size_t)BSROWS * EMB];        // [B*S, E] attn output ctx
__device__ float g_m[(size_t)BATCHN * NH * SEQ];     // row max
__device__ float g_z[(size_t)BATCHN * NH * SEQ];     // row sum-exp
// fallbacks if harness output layout differs from (out, attn) concat
__device__ float g_attn_scratch[(size_t)ATTN_ELEMS];
__device__ float g_out_scratch[(size_t)OUT_ELEMS];

// ---------------- generic 64x64 tiled SGEMM with bias ------------------------
// C[M,N] = A[M,K] @ B[K,N] + bias[N]; M,N multiples of 64, K multiple of 16.
__global__ __launch_bounds__(256) void sgemm_bias_kernel(
    const float* __restrict__ A, const float* __restrict__ B,
    const float* __restrict__ bias, float* __restrict__ C,
    int M, int N, int K)
{
    __shared__ float As[16][68];   // [k][m] (transposed)
    __shared__ float Bs[16][68];   // [k][n]
    const int tx = threadIdx.x & 15, ty = threadIdx.x >> 4;
    const int m0 = blockIdx.y * 64, n0 = blockIdx.x * 64;

    float acc[4][4] = {};
    for (int k0 = 0; k0 < K; k0 += 16) {
        for (int i = threadIdx.x; i < 1024; i += 256) {
            int r = i >> 4, c = i & 15;
            As[c][r] = A[(size_t)(m0 + r) * K + (k0 + c)];
        }
        for (int i = threadIdx.x; i < 1024; i += 256) {
            int r = i >> 6, c = i & 63;
            Bs[r][c] = B[(size_t)(k0 + r) * N + (n0 + c)];
        }
        __syncthreads();
        #pragma unroll
        for (int kk = 0; kk < 16; kk++) {
            float4 a4 = *(const float4*)&As[kk][ty * 4];
            float4 b4 = *(const float4*)&Bs[kk][tx * 4];
            float av[4] = {a4.x, a4.y, a4.z, a4.w};
            float bv[4] = {b4.x, b4.y, b4.z, b4.w};
            #pragma unroll
            for (int i = 0; i < 4; i++)
                #pragma unroll
                for (int j = 0; j < 4; j++)
                    acc[i][j] = fmaf(av[i], bv[j], acc[i][j]);
        }
        __syncthreads();
    }
    float4 bb = *(const float4*)&bias[n0 + tx * 4];
    #pragma unroll
    for (int i = 0; i < 4; i++) {
        int m = m0 + ty * 4 + i;
        float4 o;
        o.x = acc[i][0] + bb.x;
        o.y = acc[i][1] + bb.y;
        o.z = acc[i][2] + bb.z;
        o.w = acc[i][3] + bb.w;
        *(float4*)&C[(size_t)m * N + n0 + tx * 4] = o;
    }
}

// ---------------- pass A: raw scores + online row max/sumexp -----------------
// grid: (SEQ/64, B*NH). One block owns 64 query rows across all 2048 keys.
__global__ __launch_bounds__(256) void attn_scores_kernel(
    const float* __restrict__ qkv, float* __restrict__ attn)
{
    __shared__ float Qs[64][68];   // [d][q]
    __shared__ float Ks[64][68];   // [d][k]
    const int tx = threadIdx.x & 15, ty = threadIdx.x >> 4;
    const int bh = blockIdx.y;
    const int b = bh >> 4, h = bh & 15;
    const int q0 = blockIdx.x * 64;
    const float slope = exp2f(-0.5f * (float)(h + 1));

    const float* qbase = qkv + (size_t)b * SEQ * QKVN + h * (3 * HD);
    // Q tile (transposed into smem), loaded once
    for (int i = threadIdx.x; i < 4096; i += 256) {
        int q = i >> 6, d = i & 63;
        Qs[d][q] = qbase[(size_t)(q0 + q) * QKVN + d];
    }

    float mrun[4], zrun[4];
    #pragma unroll
    for (int i = 0; i < 4; i++) { mrun[i] = -3.4e38f; zrun[i] = 0.0f; }

    float* arow = attn + (size_t)bh * SEQ * SEQ;

    for (int kt = 0; kt < SEQ; kt += 64) {
        __syncthreads();
        for (int i = threadIdx.x; i < 4096; i += 256) {
            int k = i >> 6, d = i & 63;
            Ks[d][k] = qbase[(size_t)(kt + k) * QKVN + HD + d];
        }
        __syncthreads();

        float acc[4][4] = {};
        #pragma unroll 8
        for (int d = 0; d < 64; d++) {
            float4 a4 = *(const float4*)&Qs[d][ty * 4];
            float4 c4 = *(const float4*)&Ks[d][tx * 4];
            float av[4] = {a4.x, a4.y, a4.z, a4.w};
            float cv[4] = {c4.x, c4.y, c4.z, c4.w};
            #pragma unroll
            for (int i = 0; i < 4; i++)
                #pragma unroll
                for (int j = 0; j < 4; j++)
                    acc[i][j] = fmaf(av[i], cv[j], acc[i][j]);
        }

        #pragma unroll
        for (int i = 0; i < 4; i++) {
            int q = q0 + ty * 4 + i;
            float s[4];
            #pragma unroll
            for (int j = 0; j < 4; j++) {
                int k = kt + tx * 4 + j;
                s[j] = acc[i][j] * 0.125f + slope * (float)(k - q);
            }
            // row max over this 64-wide tile (16 lanes share a row)
            float lm = fmaxf(fmaxf(s[0], s[1]), fmaxf(s[2], s[3]));
            #pragma unroll
            for (int off = 8; off > 0; off >>= 1)
                lm = fmaxf(lm, __shfl_xor_sync(0xffffffffu, lm, off, 16));
            float mnew = fmaxf(mrun[i], lm);
            float se = __expf(s[0] - mnew) + __expf(s[1] - mnew) +
                       __expf(s[2] - mnew) + __expf(s[3] - mnew);
            #pragma unroll
            for (int off = 8; off > 0; off >>= 1)
                se += __shfl_xor_sync(0xffffffffu, se, off, 16);
            zrun[i] = zrun[i] * __expf(mrun[i] - mnew) + se;
            mrun[i] = mnew;

            float4 o = {s[0], s[1], s[2], s[3]};
            *(float4*)&arow[(size_t)q * SEQ + kt + tx * 4] = o;
        }
    }

    if (tx == 0) {
        #pragma unroll
        for (int i = 0; i < 4; i++) {
            int q = q0 + ty * 4 + i;
            g_m[(size_t)bh * SEQ + q] = mrun[i];
            g_z[(size_t)bh * SEQ + q] = zrun[i];
        }
    }
}

// ---------------- pass B: normalize attn in-place + O = P @ V ----------------
__global__ __launch_bounds__(256) void attn_av_kernel(
    const float* __restrict__ qkv, float* __restrict__ attn)
{
    __shared__ float Ps[64][68];   // [k][q]
    __shared__ float Vs[64][68];   // [k][d]
    __shared__ float ms[64];
    __shared__ float rz[64];
    const int tx = threadIdx.x & 15, ty = threadIdx.x >> 4;
    const int bh = blockIdx.y;
    const int b = bh >> 4, h = bh & 15;
    const int q0 = blockIdx.x * 64;

    if (threadIdx.x < 64) {
        ms[threadIdx.x] = g_m[(size_t)bh * SEQ + q0 + threadIdx.x];
        rz[threadIdx.x] = 1.0f / g_z[(size_t)bh * SEQ + q0 + threadIdx.x];
    }

    const float* vbase = qkv + (size_t)b * SEQ * QKVN + h * (3 * HD) + 2 * HD;
    float* arow = attn + (size_t)bh * SEQ * SEQ + (size_t)q0 * SEQ;

    float acc[4][4] = {};
    for (int kt = 0; kt < SEQ; kt += 64) {
        __syncthreads();
        // read raw scores, normalize, write p back, stash transposed
        for (int i = threadIdx.x; i < 1024; i += 256) {
            int r = i >> 4, c4 = (i & 15) << 2;
            float4 s = *(const float4*)&arow[(size_t)r * SEQ + kt + c4];
            float m = ms[r], z = rz[r];
            float4 p;
            p.x = __expf(s.x - m) * z;
            p.y = __expf(s.y - m) * z;
            p.z = __expf(s.z - m) * z;
            p.w = __expf(s.w - m) * z;
            *(float4*)&arow[(size_t)r * SEQ + kt + c4] = p;
            Ps[c4 + 0][r] = p.x;
            Ps[c4 + 1][r] = p.y;
            Ps[c4 + 2][r] = p.z;
            Ps[c4 + 3][r] = p.w;
        }
        for (int i = threadIdx.x; i < 4096; i += 256) {
            int k = i >> 6, d = i & 63;
            Vs[k][d] = vbase[(size_t)(kt + k) * QKVN + d];
        }
        __syncthreads();

        #pragma unroll 8
        for (int kk = 0; kk < 64; kk++) {
            float4 p4 = *(const float4*)&Ps[kk][ty * 4];
            float4 v4 = *(const float4*)&Vs[kk][tx * 4];
            float pv[4] = {p4.x, p4.y, p4.z, p4.w};
            float vv[4] = {v4.x, v4.y, v4.z, v4.w};
            #pragma unroll
            for (int i = 0; i < 4; i++)
                #pragma unroll
                for (int j = 0; j < 4; j++)
                    acc[i][j] = fmaf(pv[i], vv[j], acc[i][j]);
        }
    }

    // ctx layout [B, S, H*D] so the out-projection is a plain GEMM
    #pragma unroll
    for (int i = 0; i < 4; i++) {
        int q = q0 + ty * 4 + i;
        float4 o = {acc[i][0], acc[i][1], acc[i][2], acc[i][3]};
        *(float4*)&g_ctx[(size_t)(b * SEQ + q) * EMB + h * HD + tx * 4] = o;
    }
}

// ---------------------------------- host -------------------------------------
extern "C" void kernel_launch(void* const* d_in, const int* in_sizes, int n_in,
                              void* d_out, int out_size)
{
    const float* x    = (const float*)d_in[0];   // [B,S,E]
    const float* Wqkv = (const float*)d_in[1];   // [E,3E]
    const float* bqkv = (const float*)d_in[2];   // [3E]
    const float* Wout = (const float*)d_in[3];   // [E,E]
    const float* bout = (const float*)d_in[4];   // [E]
    float* dout = (float*)d_out;

    float* qkv;  cudaGetSymbolAddress((void**)&qkv, g_qkv);
    float* ctx;  cudaGetSymbolAddress((void**)&ctx, g_ctx);

    float* out_ptr;
    float* attn_ptr;
    if (out_size >= OUT_ELEMS + ATTN_ELEMS) {
        // concatenated (out, attn) — expected layout
        out_ptr = dout;
        attn_ptr = dout + OUT_ELEMS;
    } else if (out_size == OUT_ELEMS) {
        out_ptr = dout;
        cudaGetSymbolAddress((void**)&attn_ptr, g_attn_scratch);
    } else {
        // attn-only output
        attn_ptr = dout;
        cudaGetSymbolAddress((void**)&out_ptr, g_out_scratch);
    }

    dim3 blk(256);
    // 1) QKV projection
    sgemm_bias_kernel<<<dim3(QKVN / 64, BSROWS / 64), blk>>>(
        x, Wqkv, bqkv, qkv, BSROWS, QKVN, EMB);
    // 2) raw scores + softmax stats
    attn_scores_kernel<<<dim3(SEQ / 64, BATCHN * NH), blk>>>(qkv, attn_ptr);
    // 3) normalize attn in-place + O = P @ V
    attn_av_kernel<<<dim3(SEQ / 64, BATCHN * NH), blk>>>(qkv, attn_ptr);
    // 4) output projection
    sgemm_bias_kernel<<<dim3(EMB / 64, BSROWS / 64), blk>>>(
        ctx, Wout, bout, out_ptr, BSROWS, EMB, EMB);
}